// round 6
// baseline (speedup 1.0000x reference)
#include <cuda_runtime.h>
#include <math.h>

// ChamferLoss_31044023616212: one-sided Chamfer distance
//   set1: [2, 8192, 3] f32, set2: [2, 8192, 3] f32 -> scalar f32
//
// m_j = ||y_j||^2 - 2<x,y_j> via packed fma.rn.f32x2 (2 set2 points / op),
// d(x) = sqrt(max(min_j m_j + ||x||^2, 0)).  Same identity as reference.
//
// R6 vs 36.9us R5: L1 pipe was co-binding (56%) from 16K LDS.128/SM.
// 4x x-point register blocking (16 chunks x 32 slots x 4 pts) halves the
// LDS stream (8K/SM) while fma work is invariant -> fma-bound (~21K cyc).

#define BPB      74            // blocks per batch; 74*2 = 148 blocks (1/SM)
#define NBATCH   2
#define NBLOCKS  (BPB * NBATCH)
#define T        512
#define NCHUNK   16            // j-chunks, one per warp (chunk = warp id)
#define NSLOT    32            // x-slots (= lane id), 4 points each
#define RPAD     17            // rbuf row stride (pad vs bank conflicts)

__device__ float g_partials[NBLOCKS];
__device__ int   g_count = 0;

typedef unsigned long long u64;

__device__ __forceinline__ u64 ffma2(u64 a, u64 b, u64 c) {
    u64 d;
    asm("fma.rn.f32x2 %0, %1, %2, %3;" : "=l"(d) : "l"(a), "l"(b), "l"(c));
    return d;
}
__device__ __forceinline__ u64 bcast2(float x) {
    u64 r;
    asm("mov.b64 %0, {%1, %1};" : "=l"(r) : "f"(x));
    return r;
}
__device__ __forceinline__ void unpack2(u64 v, float& a, float& b) {
    asm("mov.b64 {%0, %1}, %2;" : "=f"(a), "=f"(b) : "l"(v));
}

extern "C" __global__ void __launch_bounds__(T, 1)
chamfer_main_kernel(const float* __restrict__ set1,
                    const float* __restrict__ set2,
                    float* __restrict__ out,
                    int n)
{
    extern __shared__ float smem[];
    float* s2   = smem;                               // n*4 floats (pair-transposed)
    float* rbuf = smem + (size_t)n * 4;               // NSLOT*4*RPAD floats
    float* ssum = rbuf + NSLOT * 4 * RPAD;            // 4 floats

    const int tid = threadIdx.x;
    const int bx  = blockIdx.x;
    const int b   = blockIdx.y;

    // ---- cooperative preprocess of set2[b] into pair-transposed SMEM ----
    // pair q = (2q, 2q+1): { ax,cx, ay,cy, az,cz, aw,cw },  a=(-2y,|y|^2)
    const float* p2 = set2 + (size_t)b * n * 3;
    for (int j = tid; j < n; j += T) {
        float y0 = p2[3 * j + 0];
        float y1 = p2[3 * j + 1];
        float y2 = p2[3 * j + 2];
        float sq = y0 * y0 + y1 * y1 + y2 * y2;
        int base = (j >> 1) * 8;
        int o    = j & 1;
        s2[base + 0 + o] = -2.0f * y0;
        s2[base + 2 + o] = -2.0f * y1;
        s2[base + 4 + o] = -2.0f * y2;
        s2[base + 6 + o] = sq;
    }
    __syncthreads();

    // ---- thread -> (x-slot = lane, j-chunk = warp): chunk warp-uniform ----
    const int w    = tid >> 5;     // 0..15 = chunk
    const int lane = tid & 31;     // 0..31 = slot

    // four set1 points per thread, strided across blocks for balance:
    //   point pt: p = (lane + 32*pt)*BPB + bx   (covered iff p < n)
    const float* base1 = set1 + (size_t)b * n * 3;
    u64 X[4][3];
    #pragma unroll
    for (int pt = 0; pt < 4; ++pt) {
        int p = (lane + (pt << 5)) * BPB + bx;
        float x0 = 0.f, x1 = 0.f, x2 = 0.f;
        if (p < n) {
            x0 = base1[3 * p + 0];
            x1 = base1[3 * p + 1];
            x2 = base1[3 * p + 2];
        }
        X[pt][0] = bcast2(x0);
        X[pt][1] = bcast2(x1);
        X[pt][2] = bcast2(x2);
    }

    const ulonglong2* sp = (const ulonglong2*)s2;  // 2 x 16B per pair
    const int npairs = n >> 1;                     // 4096
    const int QC = npairs / NCHUNK;                // 256 per chunk
    const int q0 = w * QC;

    // ---- main loop: 2 LDS.128 + 12 FFMA2 + 8 FMNMX per 8 point-pairs ----
    float mn[4][2];
    #pragma unroll
    for (int pt = 0; pt < 4; ++pt) mn[pt][0] = mn[pt][1] = 3.4e38f;

    #pragma unroll 4
    for (int q = q0; q < q0 + QC; ++q) {
        ulonglong2 u = sp[2 * q];       // {ax,cx , ay,cy}
        ulonglong2 v = sp[2 * q + 1];   // {az,cz , aw,cw}
        #pragma unroll
        for (int pt = 0; pt < 4; ++pt) {
            u64 t = ffma2(X[pt][0], u.x,
                    ffma2(X[pt][1], u.y,
                    ffma2(X[pt][2], v.x, v.y)));
            float tl, th;
            unpack2(t, tl, th);
            mn[pt][0] = fminf(mn[pt][0], tl);
            mn[pt][1] = fminf(mn[pt][1], th);
        }
    }

    // ---- per (slot,pt) chunk-mins into padded rbuf ----
    #pragma unroll
    for (int pt = 0; pt < 4; ++pt)
        rbuf[(lane * 4 + pt) * RPAD + w] = fminf(mn[pt][0], mn[pt][1]);
    __syncthreads();

    // ---- combine 16 chunks per point; threads 0..127 own one point each ----
    float dist = 0.0f;
    if (tid < NSLOT * 4) {
        const int slot = tid >> 2;
        const int pt   = tid & 3;
        float f = 3.4e38f;
        #pragma unroll
        for (int c = 0; c < NCHUNK; ++c)
            f = fminf(f, rbuf[(slot * 4 + pt) * RPAD + c]);
        const int p = (slot + (pt << 5)) * BPB + bx;
        if (p < n) {
            float a0 = base1[3 * p + 0];
            float a1 = base1[3 * p + 1];
            float a2 = base1[3 * p + 2];
            float sq = a0 * a0 + a1 * a1 + a2 * a2;
            dist = sqrtf(fmaxf(f + sq, 0.0f));
        }
        #pragma unroll
        for (int o = 16; o > 0; o >>= 1)
            dist += __shfl_xor_sync(0xffffffffu, dist, o);
        if (lane == 0) ssum[w] = dist;
    }
    __syncthreads();

    if (tid == 0) {
        float s = (ssum[0] + ssum[1]) + (ssum[2] + ssum[3]);
        g_partials[b * BPB + bx] = s;
        __threadfence();
        int t = atomicAdd(&g_count, 1);
        if (t == NBLOCKS - 1) {
            float tot = 0.0f;
            #pragma unroll 4
            for (int i = 0; i < NBLOCKS; ++i) tot += g_partials[i];
            out[0]  = tot;
            g_count = 0;    // self-reset for graph replay
        }
    }
}

extern "C" void kernel_launch(void* const* d_in, const int* in_sizes, int n_in,
                              void* d_out, int out_size)
{
    const float* set1 = (const float*)d_in[0];
    const float* set2 = (const float*)d_in[1];

    // in_sizes[0] = b * n * d = 2 * n * 3
    const int n = in_sizes[0] / (NBATCH * 3);

    const size_t smem = (size_t)n * 4 * sizeof(float)        // s2
                      + NSLOT * 4 * RPAD * sizeof(float)     // rbuf
                      + 16 * sizeof(float);                  // ssum
    cudaFuncSetAttribute(chamfer_main_kernel,
                         cudaFuncAttributeMaxDynamicSharedMemorySize, (int)smem);

    dim3 grid(BPB, NBATCH);
    chamfer_main_kernel<<<grid, T, smem>>>(set1, set2, (float*)d_out, n);
}